// round 2
// baseline (speedup 1.0000x reference)
#include <cuda_runtime.h>
#include <cuda_bf16.h>

// NMU forward: y[b,o] = prod_d ( M_hat[d,o]*x[b,d] + (1 - M_hat[d,o]) ),
// B=16384, D=256, O=32, fp32.
//
// R2 design: no shared memory.
//  - prep kernel packs clipped M pairs into g_m2[d/2][o] = (m[d],m[d+1]) and
//    complements into g_c2[d/2][o] = (1-m[d],1-m[d+1]).  Lane-o LDG.64 is
//    coalesced (256B/warp) and L1-resident (64KB total, reused ~500x).
//  - x read as LDG.128 broadcast (all lanes same address); each element
//    touched once chip-wide; no staging, no __syncthreads in main loop.
//  - packed f32x2 math at the 1-packed-inst-per-term floor:
//      t = fma(m, x, 1-m);  p *= t
//  - 4 rows/warp, 2 product chains per row (p,q) for ILP.

#define NMU_D 256
#define NMU_O 32
#define NMU_RPW 4
#define NMU_BROWS 32          // 8 warps * 4 rows

__device__ unsigned long long g_m2[(NMU_D / 2) * NMU_O];  // (m[2k],m[2k+1])
__device__ unsigned long long g_c2[(NMU_D / 2) * NMU_O];  // (1-m[2k],1-m[2k+1])

__device__ __forceinline__ unsigned long long f2_fma(unsigned long long a,
                                                     unsigned long long b,
                                                     unsigned long long c) {
    unsigned long long d;
    asm("fma.rn.f32x2 %0, %1, %2, %3;" : "=l"(d) : "l"(a), "l"(b), "l"(c));
    return d;
}
__device__ __forceinline__ unsigned long long f2_mul(unsigned long long a,
                                                     unsigned long long b) {
    unsigned long long d;
    asm("mul.rn.f32x2 %0, %1, %2;" : "=l"(d) : "l"(a), "l"(b));
    return d;
}

// ---- prep: clip + pair-pack M and (1-M) ----------------------------------
__global__ void nmu_prep(const float* __restrict__ M) {
    int i = blockIdx.x * blockDim.x + threadIdx.x;     // 0..4095
    if (i >= (NMU_D / 2) * NMU_O) return;
    int o = i & (NMU_O - 1);
    int k = i >> 5;                                    // d-pair index
    float a = __saturatef(M[(2 * k) * NMU_O + o]);
    float b = __saturatef(M[(2 * k + 1) * NMU_O + o]);
    g_m2[i] = ((unsigned long long)__float_as_uint(b) << 32) |
              (unsigned long long)__float_as_uint(a);
    g_c2[i] = ((unsigned long long)__float_as_uint(1.0f - b) << 32) |
              (unsigned long long)__float_as_uint(1.0f - a);
}

// ---- main ----------------------------------------------------------------
__global__ void __launch_bounds__(256, 3)
nmu_kernel(const float* __restrict__ x, float* __restrict__ out) {
    const int warp = threadIdx.x >> 5;
    const int o    = threadIdx.x & 31;
    const int row0 = blockIdx.x * NMU_BROWS + warp * NMU_RPW;

    const unsigned long long* __restrict__ mb = g_m2 + o;   // + k*32
    const unsigned long long* __restrict__ cb = g_c2 + o;

    unsigned long long p[NMU_RPW], q[NMU_RPW];
    const unsigned long long ONE2 = 0x3f8000003f800000ULL;
    #pragma unroll
    for (int r = 0; r < NMU_RPW; r++) { p[r] = ONE2; q[r] = ONE2; }

    const ulonglong2* __restrict__ xr[NMU_RPW];
    #pragma unroll
    for (int r = 0; r < NMU_RPW; r++)
        xr[r] = (const ulonglong2*)(x + (size_t)(row0 + r) * NMU_D);

    #pragma unroll 2
    for (int d = 0; d < NMU_D; d += 8) {
        const int k = d >> 1;
        unsigned long long m0 = __ldg(mb + (k + 0) * NMU_O);
        unsigned long long m1 = __ldg(mb + (k + 1) * NMU_O);
        unsigned long long m2 = __ldg(mb + (k + 2) * NMU_O);
        unsigned long long m3 = __ldg(mb + (k + 3) * NMU_O);
        unsigned long long c0 = __ldg(cb + (k + 0) * NMU_O);
        unsigned long long c1 = __ldg(cb + (k + 1) * NMU_O);
        unsigned long long c2 = __ldg(cb + (k + 2) * NMU_O);
        unsigned long long c3 = __ldg(cb + (k + 3) * NMU_O);

        ulonglong2 xa[NMU_RPW], xb[NMU_RPW];
        #pragma unroll
        for (int r = 0; r < NMU_RPW; r++) {
            xa[r] = __ldg(xr[r] + (d >> 2));
            xb[r] = __ldg(xr[r] + (d >> 2) + 1);
        }

        #pragma unroll
        for (int r = 0; r < NMU_RPW; r++) {
            unsigned long long t;
            t = f2_fma(m0, xa[r].x, c0);  p[r] = f2_mul(p[r], t);
            t = f2_fma(m1, xa[r].y, c1);  q[r] = f2_mul(q[r], t);
            t = f2_fma(m2, xb[r].x, c2);  p[r] = f2_mul(p[r], t);
            t = f2_fma(m3, xb[r].y, c3);  q[r] = f2_mul(q[r], t);
        }
    }

    #pragma unroll
    for (int r = 0; r < NMU_RPW; r++) {
        unsigned long long pr = f2_mul(p[r], q[r]);
        float lo = __uint_as_float((unsigned)(pr & 0xffffffffULL));
        float hi = __uint_as_float((unsigned)(pr >> 32));
        out[(size_t)(row0 + r) * NMU_O + o] = lo * hi;
    }
}

extern "C" void kernel_launch(void* const* d_in, const int* in_sizes, int n_in,
                              void* d_out, int out_size) {
    const float* x = (const float*)d_in[0];   // [16384, 256]
    const float* M = (const float*)d_in[1];   // [256, 32]
    float* out = (float*)d_out;               // [16384, 32]

    const int B = in_sizes[0] / NMU_D;        // 16384

    nmu_prep<<<((NMU_D / 2) * NMU_O + 255) / 256, 256>>>(M);
    nmu_kernel<<<B / NMU_BROWS, 256>>>(x, out);
}

// round 3
// speedup vs baseline: 1.7844x; 1.7844x over previous
#include <cuda_runtime.h>
#include <cuda_bf16.h>

// NMU forward: y[b,o] = prod_d ( M_hat[d,o]*x[b,d] + (1 - M_hat[d,o]) )
// B=16384, D=256, O=32, fp32.
//
// R3: warp-split-D, weights in registers.
//  - 8 warps/block; warp w owns d in [32w, 32w+32). lane = o.
//  - prep kernel packs (m-pair, (1-m)-pair) per (warp-chunk, pair, o) ->
//    each thread loads its 16 ulonglong2 ONCE into registers (no m traffic
//    in the hot loop).
//  - x tile (16 rows x 256) staged to smem; hot loop = broadcast LDS.128
//    (free, 1 wf) + packed f32x2 fma/mul at the 1-inst-per-term floor.
//  - per-warp partial products combined through smem (8 warps -> product).

#define NMU_D   256
#define NMU_O   32
#define NMU_R   16        // rows per block
#define NMU_NW  8         // warps per block

// packed weights: idx = ((w*16 + k)*32 + o); .x = (m[d],m[d+1]), .y = (1-m,...)
__device__ ulonglong2 g_w[NMU_NW * 16 * NMU_O];

__device__ __forceinline__ unsigned long long f2_fma(unsigned long long a,
                                                     unsigned long long b,
                                                     unsigned long long c) {
    unsigned long long d;
    asm("fma.rn.f32x2 %0, %1, %2, %3;" : "=l"(d) : "l"(a), "l"(b), "l"(c));
    return d;
}
__device__ __forceinline__ unsigned long long f2_mul(unsigned long long a,
                                                     unsigned long long b) {
    unsigned long long d;
    asm("mul.rn.f32x2 %0, %1, %2;" : "=l"(d) : "l"(a), "l"(b));
    return d;
}

// ---- prep: clip + pack M into per-warp-chunk layout -----------------------
__global__ void nmu_prep(const float* __restrict__ M) {
    int i = blockIdx.x * blockDim.x + threadIdx.x;      // 0..4095
    if (i >= NMU_NW * 16 * NMU_O) return;
    int o = i & 31;
    int k = (i >> 5) & 15;      // pair index within chunk
    int w = i >> 9;             // d-chunk (warp) index
    int d0 = w * 32 + 2 * k;
    float a = __saturatef(M[d0 * NMU_O + o]);
    float b = __saturatef(M[(d0 + 1) * NMU_O + o]);
    ulonglong2 v;
    v.x = ((unsigned long long)__float_as_uint(b) << 32) |
          (unsigned long long)__float_as_uint(a);
    v.y = ((unsigned long long)__float_as_uint(1.0f - b) << 32) |
          (unsigned long long)__float_as_uint(1.0f - a);
    g_w[i] = v;
}

// ---- main -----------------------------------------------------------------
__global__ void __launch_bounds__(256, 2)
nmu_kernel(const float* __restrict__ x, float* __restrict__ out) {
    __shared__ float xs[NMU_R * NMU_D];            // 16 KB
    __shared__ float pw[NMU_NW * NMU_R * NMU_O];   // 16 KB

    const int tid  = threadIdx.x;
    const int warp = tid >> 5;
    const int o    = tid & 31;
    const int b0   = blockIdx.x * NMU_R;

    // --- weights into registers (coalesced LDG.128 x16, once per block) ---
    unsigned long long m[16], c[16];
    {
        const ulonglong2* __restrict__ gw = g_w + warp * 16 * NMU_O + o;
        #pragma unroll
        for (int k = 0; k < 16; k++) {
            ulonglong2 v = __ldg(gw + k * NMU_O);
            m[k] = v.x;
            c[k] = v.y;
        }
    }

    // --- stage x tile (coalesced) ---
    {
        const float4* __restrict__ xg = (const float4*)(x + (size_t)b0 * NMU_D);
        float4* xs4 = (float4*)xs;
        #pragma unroll
        for (int i = 0; i < (NMU_R * NMU_D / 4) / 256; i++)   // 4 iters
            xs4[tid + i * 256] = xg[tid + i * 256];
    }
    __syncthreads();

    // --- hot loop: one row at a time, 2 product chains ---
    const unsigned long long ONE2 = 0x3f8000003f800000ULL;
    #pragma unroll 2
    for (int r = 0; r < NMU_R; r++) {
        const ulonglong2* __restrict__ xr =
            (const ulonglong2*)(xs + r * NMU_D + warp * 32);
        ulonglong2 v0 = xr[0], v1 = xr[1], v2 = xr[2], v3 = xr[3];
        ulonglong2 v4 = xr[4], v5 = xr[5], v6 = xr[6], v7 = xr[7];

        unsigned long long p = ONE2, q = ONE2, t;
        t = f2_fma(m[ 0], v0.x, c[ 0]);  p = f2_mul(p, t);
        t = f2_fma(m[ 1], v0.y, c[ 1]);  q = f2_mul(q, t);
        t = f2_fma(m[ 2], v1.x, c[ 2]);  p = f2_mul(p, t);
        t = f2_fma(m[ 3], v1.y, c[ 3]);  q = f2_mul(q, t);
        t = f2_fma(m[ 4], v2.x, c[ 4]);  p = f2_mul(p, t);
        t = f2_fma(m[ 5], v2.y, c[ 5]);  q = f2_mul(q, t);
        t = f2_fma(m[ 6], v3.x, c[ 6]);  p = f2_mul(p, t);
        t = f2_fma(m[ 7], v3.y, c[ 7]);  q = f2_mul(q, t);
        t = f2_fma(m[ 8], v4.x, c[ 8]);  p = f2_mul(p, t);
        t = f2_fma(m[ 9], v4.y, c[ 9]);  q = f2_mul(q, t);
        t = f2_fma(m[10], v5.x, c[10]);  p = f2_mul(p, t);
        t = f2_fma(m[11], v5.y, c[11]);  q = f2_mul(q, t);
        t = f2_fma(m[12], v6.x, c[12]);  p = f2_mul(p, t);
        t = f2_fma(m[13], v6.y, c[13]);  q = f2_mul(q, t);
        t = f2_fma(m[14], v7.x, c[14]);  p = f2_mul(p, t);
        t = f2_fma(m[15], v7.y, c[15]);  q = f2_mul(q, t);

        unsigned long long pr = f2_mul(p, q);
        float lo = __uint_as_float((unsigned)(pr & 0xffffffffULL));
        float hi = __uint_as_float((unsigned)(pr >> 32));
        pw[(warp * NMU_R + r) * NMU_O + o] = lo * hi;   // conflict-free STS.32
    }
    __syncthreads();

    // --- combine 8 warp-partials per (row, o); 2 outputs per thread ---
    #pragma unroll
    for (int i = 0; i < 2; i++) {
        int idx = tid + i * 256;            // 0..511
        int row = idx >> 5;
        int oo  = idx & 31;
        const float* pp = pw + row * NMU_O + oo;
        float a0 = pp[0 * NMU_R * NMU_O] * pp[1 * NMU_R * NMU_O];
        float a1 = pp[2 * NMU_R * NMU_O] * pp[3 * NMU_R * NMU_O];
        float a2 = pp[4 * NMU_R * NMU_O] * pp[5 * NMU_R * NMU_O];
        float a3 = pp[6 * NMU_R * NMU_O] * pp[7 * NMU_R * NMU_O];
        out[(size_t)(b0 + row) * NMU_O + oo] = (a0 * a1) * (a2 * a3);
    }
}

extern "C" void kernel_launch(void* const* d_in, const int* in_sizes, int n_in,
                              void* d_out, int out_size) {
    const float* x = (const float*)d_in[0];   // [16384, 256]
    const float* M = (const float*)d_in[1];   // [256, 32]
    float* out = (float*)d_out;               // [16384, 32]

    const int B = in_sizes[0] / NMU_D;        // 16384

    nmu_prep<<<(NMU_NW * 16 * NMU_O + 255) / 256, 256>>>(M);
    nmu_kernel<<<B / NMU_R, 256>>>(x, out);
}

// round 4
// speedup vs baseline: 1.9713x; 1.1047x over previous
#include <cuda_runtime.h>
#include <cuda_bf16.h>

// NMU forward: y[b,o] = prod_d ( M_hat[d,o]*x[b,d] + (1 - M_hat[d,o]) )
// B=16384, D=256, O=32, fp32.
//
// R4: warp-split-D with 16 warps x 16 d's, fused M-prep, 50% occupancy.
//  - block = 512 threads (16 warps), warp w owns d in [16w, 16w+16), lane = o.
//  - each thread clips+packs its 8 (m,1-m) f32x2 pairs straight from M
//    (16 coalesced LDGs once per block; no separate prep kernel).
//  - x tile (16 rows x 256) staged in smem; hot loop = 4 broadcast LDS.128
//    + 8 packed fma + 8 packed mul per row (1 packed inst per 2 terms).
//  - per-warp partials -> smem -> 16-way product combine, 1 output/thread.

#define NMU_D   256
#define NMU_O   32
#define NMU_R   16        // rows per block
#define NMU_NW  16        // warps per block
#define NMU_DPW 16        // d's per warp

__device__ __forceinline__ unsigned long long f2_fma(unsigned long long a,
                                                     unsigned long long b,
                                                     unsigned long long c) {
    unsigned long long d;
    asm("fma.rn.f32x2 %0, %1, %2, %3;" : "=l"(d) : "l"(a), "l"(b), "l"(c));
    return d;
}
__device__ __forceinline__ unsigned long long f2_mul(unsigned long long a,
                                                     unsigned long long b) {
    unsigned long long d;
    asm("mul.rn.f32x2 %0, %1, %2;" : "=l"(d) : "l"(a), "l"(b));
    return d;
}
__device__ __forceinline__ unsigned long long pack2(float a, float b) {
    return ((unsigned long long)__float_as_uint(b) << 32) |
           (unsigned long long)__float_as_uint(a);
}

__global__ void __launch_bounds__(512, 2)
nmu_kernel(const float* __restrict__ x, const float* __restrict__ M,
           float* __restrict__ out) {
    __shared__ float xs[NMU_R * NMU_D];            // 16 KB
    __shared__ float pw[NMU_NW * NMU_R * NMU_O];   // 32 KB  (total 48 KB)

    const int tid  = threadIdx.x;
    const int warp = tid >> 5;
    const int o    = tid & 31;
    const int b0   = blockIdx.x * NMU_R;
    const int d0   = warp * NMU_DPW;

    // --- weights into registers: 8 packed (m, 1-m) pairs ---
    unsigned long long m2[8], c2[8];
    {
        const float* __restrict__ Mg = M + (size_t)d0 * NMU_O + o;
        #pragma unroll
        for (int k = 0; k < 8; k++) {
            float a = __saturatef(Mg[(2 * k + 0) * NMU_O]);
            float b = __saturatef(Mg[(2 * k + 1) * NMU_O]);
            m2[k] = pack2(a, b);
            c2[k] = pack2(1.0f - a, 1.0f - b);
        }
    }

    // --- stage x tile (coalesced float4) ---
    {
        const float4* __restrict__ xg = (const float4*)(x + (size_t)b0 * NMU_D);
        float4* xs4 = (float4*)xs;
        #pragma unroll
        for (int i = 0; i < (NMU_R * NMU_D / 4) / 512; i++)   // 2 iters
            xs4[tid + i * 512] = xg[tid + i * 512];
    }
    __syncthreads();

    // --- hot loop: 16 rows, 2 product chains, broadcast LDS.128 ---
    #pragma unroll 4
    for (int r = 0; r < NMU_R; r++) {
        const ulonglong2* __restrict__ xr =
            (const ulonglong2*)(xs + r * NMU_D + d0);
        ulonglong2 v0 = xr[0], v1 = xr[1], v2 = xr[2], v3 = xr[3];

        unsigned long long p, q, t;
        t = f2_fma(m2[0], v0.x, c2[0]);  p = t;
        t = f2_fma(m2[1], v0.y, c2[1]);  q = t;
        t = f2_fma(m2[2], v1.x, c2[2]);  p = f2_mul(p, t);
        t = f2_fma(m2[3], v1.y, c2[3]);  q = f2_mul(q, t);
        t = f2_fma(m2[4], v2.x, c2[4]);  p = f2_mul(p, t);
        t = f2_fma(m2[5], v2.y, c2[5]);  q = f2_mul(q, t);
        t = f2_fma(m2[6], v3.x, c2[6]);  p = f2_mul(p, t);
        t = f2_fma(m2[7], v3.y, c2[7]);  q = f2_mul(q, t);

        unsigned long long pr = f2_mul(p, q);
        float lo = __uint_as_float((unsigned)(pr & 0xffffffffULL));
        float hi = __uint_as_float((unsigned)(pr >> 32));
        pw[(warp * NMU_R + r) * NMU_O + o] = lo * hi;   // conflict-free STS.32
    }
    __syncthreads();

    // --- combine 16 warp-partials; 1 output per thread ---
    {
        int row = tid >> 5;          // 0..15
        int oo  = tid & 31;
        const float* pp = pw + row * NMU_O + oo;
        const int S = NMU_R * NMU_O; // 512 floats between warp slabs
        float a0 = pp[ 0 * S] * pp[ 1 * S];
        float a1 = pp[ 2 * S] * pp[ 3 * S];
        float a2 = pp[ 4 * S] * pp[ 5 * S];
        float a3 = pp[ 6 * S] * pp[ 7 * S];
        float a4 = pp[ 8 * S] * pp[ 9 * S];
        float a5 = pp[10 * S] * pp[11 * S];
        float a6 = pp[12 * S] * pp[13 * S];
        float a7 = pp[14 * S] * pp[15 * S];
        float r0 = (a0 * a1) * (a2 * a3);
        float r1 = (a4 * a5) * (a6 * a7);
        out[(size_t)(b0 + row) * NMU_O + oo] = r0 * r1;
    }
}

extern "C" void kernel_launch(void* const* d_in, const int* in_sizes, int n_in,
                              void* d_out, int out_size) {
    const float* x = (const float*)d_in[0];   // [16384, 256]
    const float* M = (const float*)d_in[1];   // [256, 32]
    float* out = (float*)d_out;               // [16384, 32]

    const int B = in_sizes[0] / NMU_D;        // 16384

    nmu_kernel<<<B / NMU_R, 512>>>(x, M, out);
}

// round 5
// speedup vs baseline: 2.2144x; 1.1233x over previous
#include <cuda_runtime.h>
#include <cuda_bf16.h>

// NMU forward: y[b,o] = prod_d ( M_hat[d,o]*x[b,d] + (1 - M_hat[d,o]) )
//            = prod_d ( M_hat[d,o]*(x[b,d]-1) + 1 )
// B=16384, D=256, O=32, fp32.
//
// R5: u = x-1 staged in smem (kills the (1-m) register array), warp owns
// 32 d's with 16 packed m-pairs in registers, 8-warp blocks, 8 rows/block,
// 4 blocks/SM. Hot loop: broadcast LDS.128 of u + packed f32x2 fma/mul.
// 8-wide partial-product combine through smem.

#define NMU_D   256
#define NMU_O   32
#define NMU_R   8         // rows per block
#define NMU_NW  8         // warps per block
#define NMU_DPW 32        // d's per warp

__device__ __forceinline__ unsigned long long f2_fma(unsigned long long a,
                                                     unsigned long long b,
                                                     unsigned long long c) {
    unsigned long long d;
    asm("fma.rn.f32x2 %0, %1, %2, %3;" : "=l"(d) : "l"(a), "l"(b), "l"(c));
    return d;
}
__device__ __forceinline__ unsigned long long f2_mul(unsigned long long a,
                                                     unsigned long long b) {
    unsigned long long d;
    asm("mul.rn.f32x2 %0, %1, %2;" : "=l"(d) : "l"(a), "l"(b));
    return d;
}
__device__ __forceinline__ unsigned long long pack2(float a, float b) {
    return ((unsigned long long)__float_as_uint(b) << 32) |
           (unsigned long long)__float_as_uint(a);
}

__global__ void __launch_bounds__(256, 4)
nmu_kernel(const float* __restrict__ x, const float* __restrict__ M,
           float* __restrict__ out) {
    __shared__ float us[NMU_R * NMU_D];            // 8 KB  (x - 1)
    __shared__ float pw[NMU_NW * NMU_R * NMU_O];   // 8 KB  partials

    const int tid  = threadIdx.x;
    const int warp = tid >> 5;
    const int o    = tid & 31;
    const int b0   = blockIdx.x * NMU_R;
    const int d0   = warp * NMU_DPW;

    // --- weights: 16 packed m-pairs into registers (coalesced, L1/L2-hot) ---
    unsigned long long m2[16];
    {
        const float* __restrict__ Mg = M + (size_t)d0 * NMU_O + o;
        #pragma unroll
        for (int k = 0; k < 16; k++) {
            float a = __saturatef(__ldg(Mg + (2 * k + 0) * NMU_O));
            float b = __saturatef(__ldg(Mg + (2 * k + 1) * NMU_O));
            m2[k] = pack2(a, b);
        }
    }

    // --- stage u = x - 1 (coalesced float4, subtract folded into copy) ---
    {
        const float4* __restrict__ xg = (const float4*)(x + (size_t)b0 * NMU_D);
        float4* us4 = (float4*)us;
        #pragma unroll
        for (int i = 0; i < (NMU_R * NMU_D / 4) / 256; i++) {   // 2 iters
            float4 v = xg[tid + i * 256];
            v.x -= 1.0f; v.y -= 1.0f; v.z -= 1.0f; v.w -= 1.0f;
            us4[tid + i * 256] = v;
        }
    }
    __syncthreads();

    // --- hot loop: 8 rows; per row two 16-d half-chunks ---
    const unsigned long long ONE2 = 0x3f8000003f800000ULL;
    #pragma unroll 2
    for (int r = 0; r < NMU_R; r++) {
        const ulonglong2* __restrict__ ur =
            (const ulonglong2*)(us + r * NMU_D + d0);

        unsigned long long p, q, t;
        // half-chunk 0: d0 .. d0+15
        {
            ulonglong2 v0 = ur[0], v1 = ur[1], v2 = ur[2], v3 = ur[3];
            t = f2_fma(m2[0], v0.x, ONE2);  p = t;
            t = f2_fma(m2[1], v0.y, ONE2);  q = t;
            t = f2_fma(m2[2], v1.x, ONE2);  p = f2_mul(p, t);
            t = f2_fma(m2[3], v1.y, ONE2);  q = f2_mul(q, t);
            t = f2_fma(m2[4], v2.x, ONE2);  p = f2_mul(p, t);
            t = f2_fma(m2[5], v2.y, ONE2);  q = f2_mul(q, t);
            t = f2_fma(m2[6], v3.x, ONE2);  p = f2_mul(p, t);
            t = f2_fma(m2[7], v3.y, ONE2);  q = f2_mul(q, t);
        }
        // half-chunk 1: d0+16 .. d0+31
        {
            ulonglong2 v4 = ur[4], v5 = ur[5], v6 = ur[6], v7 = ur[7];
            t = f2_fma(m2[ 8], v4.x, ONE2);  p = f2_mul(p, t);
            t = f2_fma(m2[ 9], v4.y, ONE2);  q = f2_mul(q, t);
            t = f2_fma(m2[10], v5.x, ONE2);  p = f2_mul(p, t);
            t = f2_fma(m2[11], v5.y, ONE2);  q = f2_mul(q, t);
            t = f2_fma(m2[12], v6.x, ONE2);  p = f2_mul(p, t);
            t = f2_fma(m2[13], v6.y, ONE2);  q = f2_mul(q, t);
            t = f2_fma(m2[14], v7.x, ONE2);  p = f2_mul(p, t);
            t = f2_fma(m2[15], v7.y, ONE2);  q = f2_mul(q, t);
        }

        unsigned long long pr = f2_mul(p, q);
        float lo = __uint_as_float((unsigned)(pr & 0xffffffffULL));
        float hi = __uint_as_float((unsigned)(pr >> 32));
        pw[(warp * NMU_R + r) * NMU_O + o] = lo * hi;   // conflict-free STS.32
    }
    __syncthreads();

    // --- combine 8 warp-partials; exactly 1 output per thread ---
    {
        const int row = tid >> 5;          // 0..7
        const int oo  = tid & 31;
        const float* pp = pw + row * NMU_O + oo;
        const int S = NMU_R * NMU_O;       // 256 floats between warp slabs
        float a0 = pp[0 * S] * pp[1 * S];
        float a1 = pp[2 * S] * pp[3 * S];
        float a2 = pp[4 * S] * pp[5 * S];
        float a3 = pp[6 * S] * pp[7 * S];
        out[(size_t)(b0 + row) * NMU_O + oo] = (a0 * a1) * (a2 * a3);
    }
}

extern "C" void kernel_launch(void* const* d_in, const int* in_sizes, int n_in,
                              void* d_out, int out_size) {
    const float* x = (const float*)d_in[0];   // [16384, 256]
    const float* M = (const float*)d_in[1];   // [256, 32]
    float* out = (float*)d_out;               // [16384, 32]

    const int B = in_sizes[0] / NMU_D;        // 16384

    nmu_kernel<<<B / NMU_R, 256>>>(x, M, out);
}